// round 7
// baseline (speedup 1.0000x reference)
#include <cuda_runtime.h>

// FINAL: out[i] = cos(x[i]).
//
// Analytical collapse of the 4-wire / 4-layer RY-RZ-CNOT circuit:
//   * RZ layers are diagonal unit-modulus phases -> |amp|^2 unchanged.
//   * The CNOT chain 0->1->2->3 is the GF(2) linear map T (lower-triangular
//     ones); T^2 = I + S2, T^4 = I, so 4 layers permute basis states back to
//     identity. Probabilities stay the initial product state.
//   * <Z_w> = cos^2(x_w/2) - sin^2(x_w/2) = cos(x_w). weights unused.
//
// Perf summary (GB300, sm_103a): six body variants (libm cosf, MUFU ILP1/2/4,
// TMA bulk pipeline, streaming stores) all pin total dur at 6.6-6.9 us while
// ncu kernel time varies 4.9-5.7 us -> the benchmark is at the fixed
// graph-replay + launch (T_ovh ~5000 cyc) floor; all pipes <= 11%. This is
// the best-measured configuration: ILP=2 float4/thread, 512x256, MUFU.COS,
// evict-first streaming stores (write-only output doesn't pollute L2).

__global__ void __launch_bounds__(256) qk_cos_final(const float4* __restrict__ x,
                                                    float4* __restrict__ out, int n4) {
    int i = (blockIdx.x * blockDim.x + threadIdx.x) * 2;
    if (i + 1 < n4) {
        // front-batch both 128-bit loads (MLP=2)
        float4 v0 = x[i];
        float4 v1 = x[i + 1];
        float4 r0, r1;
        r0.x = __cosf(v0.x); r0.y = __cosf(v0.y);
        r0.z = __cosf(v0.z); r0.w = __cosf(v0.w);
        r1.x = __cosf(v1.x); r1.y = __cosf(v1.y);
        r1.z = __cosf(v1.z); r1.w = __cosf(v1.w);
        __stcs(&out[i],     r0);
        __stcs(&out[i + 1], r1);
    } else if (i < n4) {
        float4 v0 = x[i];
        float4 r0;
        r0.x = __cosf(v0.x); r0.y = __cosf(v0.y);
        r0.z = __cosf(v0.z); r0.w = __cosf(v0.w);
        __stcs(&out[i], r0);
    }
}

// Safety net for element counts not divisible by 4 (never launched for this
// problem's shape, so it adds no graph nodes).
__global__ void qk_cos_tail(const float* __restrict__ x, float* __restrict__ out,
                            int start, int n) {
    int i = start + blockIdx.x * blockDim.x + threadIdx.x;
    if (i < n) out[i] = __cosf(x[i]);
}

extern "C" void kernel_launch(void* const* d_in, const int* in_sizes, int n_in,
                              void* d_out, int out_size) {
    const float* x = (const float*)d_in[0];   // (262144, 4) float32
    float* out = (float*)d_out;
    int n = out_size;          // 1,048,576
    int n4 = n >> 2;           // 262,144 float4s

    const int T = 256;
    int threads_needed = (n4 + 1) >> 1;        // ILP=2
    int blocks = (threads_needed + T - 1) / T; // 512
    qk_cos_final<<<blocks, T>>>((const float4*)x, (float4*)out, n4);

    int rem = n - (n4 << 2);
    if (rem > 0) qk_cos_tail<<<1, 32>>>(x, out, n4 << 2, n);
}

// round 8
// speedup vs baseline: 1.0047x; 1.0047x over previous
#include <cuda_runtime.h>
#include <cstdint>

// out[i] = cos(x[i]).
//
// Analytical collapse of the 4-wire / 4-layer RY-RZ-CNOT circuit:
//   * RZ layers are diagonal unit-modulus phases -> |amp|^2 unchanged.
//   * CNOT chain 0->1->2->3 = GF(2) map T (lower-triangular ones); T^4 = I,
//     so 4 layers return the basis permutation to identity.
//   * <Z_w> = cos^2(x_w/2) - sin^2(x_w/2) = cos(x_w). weights unused.
//
// R8: 256-bit global accesses (LDG.E.256 / STG.E.256, sm_100+), halving LSU
// transactions at the best-measured launch shape (512x256). Everything else
// is pinned at the graph-replay + launch-overhead floor (~6.6us total).

__global__ void __launch_bounds__(256) qk_cos_v8(const float* __restrict__ x,
                                                 float* __restrict__ out, int n) {
    int t = blockIdx.x * blockDim.x + threadIdx.x;
    long long base = (long long)t * 8;
    if (base + 8 <= n) {
        float a0, a1, a2, a3, a4, a5, a6, a7;
        asm volatile("ld.global.nc.v8.f32 {%0,%1,%2,%3,%4,%5,%6,%7}, [%8];"
                     : "=f"(a0), "=f"(a1), "=f"(a2), "=f"(a3),
                       "=f"(a4), "=f"(a5), "=f"(a6), "=f"(a7)
                     : "l"(x + base));
        a0 = __cosf(a0); a1 = __cosf(a1); a2 = __cosf(a2); a3 = __cosf(a3);
        a4 = __cosf(a4); a5 = __cosf(a5); a6 = __cosf(a6); a7 = __cosf(a7);
        asm volatile("st.global.cs.v8.f32 [%0], {%1,%2,%3,%4,%5,%6,%7,%8};"
                     :: "l"(out + base),
                        "f"(a0), "f"(a1), "f"(a2), "f"(a3),
                        "f"(a4), "f"(a5), "f"(a6), "f"(a7)
                     : "memory");
    } else {
        for (long long j = base; j < n; j++) out[j] = __cosf(x[j]);
    }
}

extern "C" void kernel_launch(void* const* d_in, const int* in_sizes, int n_in,
                              void* d_out, int out_size) {
    const float* x = (const float*)d_in[0];   // (262144, 4) float32
    float* out = (float*)d_out;
    int n = out_size;                          // 1,048,576

    const int T = 256;
    int threads_needed = (n + 7) >> 3;         // 8 floats per thread
    int blocks = (threads_needed + T - 1) / T; // 512
    qk_cos_v8<<<blocks, T>>>(x, out, n);
}

// round 9
// speedup vs baseline: 1.0337x; 1.0288x over previous
#include <cuda_runtime.h>

// FINAL: out[i] = cos(x[i]).
//
// Analytical collapse of the 4-wire / 4-layer RY-RZ-CNOT circuit:
//   * RZ layers are diagonal unit-modulus phases -> |amplitude|^2 unchanged;
//     the output depends only on probabilities.
//   * The CNOT chain 0->1, 1->2, 2->3 acts on basis-index bits as the GF(2)
//     linear map T (lower-triangular all-ones). T^2 = I + S2 (shift-by-2),
//     so T^4 = I + S2^2 = I in 4 dims: after the 4 layers the basis
//     permutation is the identity.
//   * Probabilities therefore remain the initial RY product state:
//     <Z_w> = cos^2(x_w/2) - sin^2(x_w/2) = cos(x_w). weights are unused.
//
// Perf conclusion (8 rounds, GB300 sm_103a): eight body variants — libm cosf,
// MUFU ILP1/2/4, TMA cp.async.bulk pipeline, streaming stores, 256-bit
// LDG/STG — all land at 6.6-6.9 us total while ncu kernel time varies
// 4.9-5.7 us. All pipes <= 11% of peak. The benchmark is pinned at the fixed
// graph-replay + launch-overhead (T_ovh ~5000 cyc) floor; the 8 MB of LTS
// traffic is a minor additive term. This is the best-measured configuration:
// ILP=2 float4/thread (front-batched LDG.128 x2), 512 blocks x 256 threads,
// MUFU.COS (abs err ~2^-21 for N(0,1) inputs, rel_err 2.2e-7 << 1e-3),
// evict-first streaming stores so the write-only output doesn't evict the
// L2-resident input across graph replays.

__global__ void __launch_bounds__(256) qk_cos_final(const float4* __restrict__ x,
                                                    float4* __restrict__ out, int n4) {
    int i = (blockIdx.x * blockDim.x + threadIdx.x) * 2;
    if (i + 1 < n4) {
        // front-batch both 128-bit loads (MLP=2)
        float4 v0 = x[i];
        float4 v1 = x[i + 1];
        float4 r0, r1;
        r0.x = __cosf(v0.x); r0.y = __cosf(v0.y);
        r0.z = __cosf(v0.z); r0.w = __cosf(v0.w);
        r1.x = __cosf(v1.x); r1.y = __cosf(v1.y);
        r1.z = __cosf(v1.z); r1.w = __cosf(v1.w);
        __stcs(&out[i],     r0);
        __stcs(&out[i + 1], r1);
    } else if (i < n4) {
        float4 v0 = x[i];
        float4 r0;
        r0.x = __cosf(v0.x); r0.y = __cosf(v0.y);
        r0.z = __cosf(v0.z); r0.w = __cosf(v0.w);
        __stcs(&out[i], r0);
    }
}

// Safety net for element counts not divisible by 4 (never launched for this
// problem's shape, so it adds no graph nodes).
__global__ void qk_cos_tail(const float* __restrict__ x, float* __restrict__ out,
                            int start, int n) {
    int i = start + blockIdx.x * blockDim.x + threadIdx.x;
    if (i < n) out[i] = __cosf(x[i]);
}

extern "C" void kernel_launch(void* const* d_in, const int* in_sizes, int n_in,
                              void* d_out, int out_size) {
    const float* x = (const float*)d_in[0];   // (262144, 4) float32
    float* out = (float*)d_out;
    int n = out_size;          // 1,048,576
    int n4 = n >> 2;           // 262,144 float4s

    const int T = 256;
    int threads_needed = (n4 + 1) >> 1;        // ILP=2
    int blocks = (threads_needed + T - 1) / T; // 512
    qk_cos_final<<<blocks, T>>>((const float4*)x, (float4*)out, n4);

    int rem = n - (n4 << 2);
    if (rem > 0) qk_cos_tail<<<1, 32>>>(x, out, n4 << 2, n);
}

// round 10
// speedup vs baseline: 1.0386x; 1.0048x over previous
#include <cuda_runtime.h>

// FINAL (locked, R9-verified): out[i] = cos(x[i]).
//
// Analytical collapse of the 4-wire / 4-layer RY-RZ-CNOT circuit:
//   * RZ layers are diagonal unit-modulus phases -> |amplitude|^2 unchanged;
//     the output depends only on probabilities.
//   * The CNOT chain 0->1, 1->2, 2->3 acts on basis-index bits as the GF(2)
//     linear map T (lower-triangular all-ones). T^2 = I + S2 (shift-by-2),
//     so T^4 = I + S2^2 = I in 4 dims: after the 4 layers the basis
//     permutation is the identity.
//   * Probabilities therefore remain the initial RY product state:
//     <Z_w> = cos^2(x_w/2) - sin^2(x_w/2) = cos(x_w). weights are unused.
//
// Perf conclusion (9 rounds, GB300 sm_103a): eight body variants — libm cosf,
// MUFU ILP1/2/4, TMA cp.async.bulk pipeline, streaming stores, 256-bit
// LDG/STG — all land at 6.6-6.9 us total while ncu kernel time varies
// 4.8-5.7 us with zero correlation to the total. All pipes <= 11% of peak.
// The benchmark is pinned at the fixed graph-replay + launch-overhead
// (T_ovh ~5000 cyc) floor; the 8 MB of LTS traffic is a minor additive term.
// Best-measured configuration (kernel 4.832 us, total 6.656 us):
//   - ILP=2 float4/thread, front-batched LDG.128 x2 (MLP=2)
//   - 512 blocks x 256 threads
//   - MUFU.COS (__cosf): abs err ~2^-21 on N(0,1) inputs, rel_err 2.2e-7
//   - __stcs evict-first streaming stores: write-only output doesn't evict
//     the L2-resident input across graph replays.

__global__ void __launch_bounds__(256) qk_cos_final(const float4* __restrict__ x,
                                                    float4* __restrict__ out, int n4) {
    int i = (blockIdx.x * blockDim.x + threadIdx.x) * 2;
    if (i + 1 < n4) {
        // front-batch both 128-bit loads (MLP=2)
        float4 v0 = x[i];
        float4 v1 = x[i + 1];
        float4 r0, r1;
        r0.x = __cosf(v0.x); r0.y = __cosf(v0.y);
        r0.z = __cosf(v0.z); r0.w = __cosf(v0.w);
        r1.x = __cosf(v1.x); r1.y = __cosf(v1.y);
        r1.z = __cosf(v1.z); r1.w = __cosf(v1.w);
        __stcs(&out[i],     r0);
        __stcs(&out[i + 1], r1);
    } else if (i < n4) {
        float4 v0 = x[i];
        float4 r0;
        r0.x = __cosf(v0.x); r0.y = __cosf(v0.y);
        r0.z = __cosf(v0.z); r0.w = __cosf(v0.w);
        __stcs(&out[i], r0);
    }
}

// Safety net for element counts not divisible by 4 (never launched for this
// problem's shape, so it adds no graph nodes).
__global__ void qk_cos_tail(const float* __restrict__ x, float* __restrict__ out,
                            int start, int n) {
    int i = start + blockIdx.x * blockDim.x + threadIdx.x;
    if (i < n) out[i] = __cosf(x[i]);
}

extern "C" void kernel_launch(void* const* d_in, const int* in_sizes, int n_in,
                              void* d_out, int out_size) {
    const float* x = (const float*)d_in[0];   // (262144, 4) float32
    float* out = (float*)d_out;
    int n = out_size;          // 1,048,576
    int n4 = n >> 2;           // 262,144 float4s

    const int T = 256;
    int threads_needed = (n4 + 1) >> 1;        // ILP=2
    int blocks = (threads_needed + T - 1) / T; // 512
    qk_cos_final<<<blocks, T>>>((const float4*)x, (float4*)out, n4);

    int rem = n - (n4 << 2);
    if (rem > 0) qk_cos_tail<<<1, 32>>>(x, out, n4 << 2, n);
}